// round 3
// baseline (speedup 1.0000x reference)
#include <cuda_runtime.h>
#include <math.h>

#define Bn 32
#define Sn 2048
#define En 1024
#define Hn 1024

// scratch (no cudaMalloc allowed)
__device__ float g_colsum[Hn];        // sum_g M_w[g, E+h]
__device__ float g_hidc[Bn * Hn];     // hidden[b,h]*colsum[h] + M_b[h]
__device__ float g_scores[Bn * Sn];   // pre-softmax scores

// ---------------------------------------------------------------------------
// Kernel 0: zero the weighted-output region (d_out poisoned to 0xAA)
// ---------------------------------------------------------------------------
__global__ void zero_out_kernel(float* __restrict__ out, int n) {
    int i = blockIdx.x * blockDim.x + threadIdx.x;
    if (i < n) out[i] = 0.0f;
}

// ---------------------------------------------------------------------------
// Kernel 1a: g_colsum[h] = sum_g M_w[g, E+h]
// ---------------------------------------------------------------------------
__global__ void colsum_kernel(const float* __restrict__ Mw) {
    const int h = blockIdx.x * blockDim.x + threadIdx.x;
    if (h >= Hn) return;
    const float* p = Mw + En + h;        // column E+h, row stride E+H
    float acc = 0.0f;
#pragma unroll 8
    for (int g = 0; g < Hn; ++g)
        acc += p[(size_t)g * (En + Hn)];
    g_colsum[h] = acc;
}

// ---------------------------------------------------------------------------
// Kernel 1b: g_hidc[b,h] = hidden[b,0,h] * colsum[h] + M_b[h]
// (reference einsum 'boh,hg->boh' keeps h free and sums over g)
// ---------------------------------------------------------------------------
__global__ void hidc_kernel(const float* __restrict__ hidden,
                            const float* __restrict__ Mb) {
    const int i = blockIdx.x * blockDim.x + threadIdx.x;
    if (i >= Bn * Hn) return;
    const int h = i & (Hn - 1);
    g_hidc[i] = fmaf(hidden[i], g_colsum[h], Mb[h]);
}

// ---------------------------------------------------------------------------
// Kernel 2: fused scores GEMM
//   scores[b,s] = V_b + sum_h V_w[h] * tanh( enc[b,s,:] . M_w[h,:E] + hidc[b,h] )
// ---------------------------------------------------------------------------
#define BM 64
#define BN 64
#define BK 16

__global__ __launch_bounds__(256, 2)
void scores_kernel(const float* __restrict__ enc,
                   const float* __restrict__ Mw,
                   const float* __restrict__ Vw,
                   const float* __restrict__ Vb) {
    __shared__ float As[BK][BM];   // enc tile, transposed: As[k][m]
    __shared__ float Bs[BK][BN];   // Mw tile, transposed: Bs[k][n]

    const int m0 = blockIdx.x * BM;      // global row in [0, B*S)
    const int b  = m0 / Sn;              // BM divides S, block never spans b
    const int tid = threadIdx.x;
    const int tx = tid & 15;             // 0..15 -> n sub-tile
    const int ty = tid >> 4;             // 0..15 -> m sub-tile

    const int lrow = tid >> 2;           // 0..63
    const int lcg  = (tid & 3) * 4;      // 0,4,8,12

    float rowsum[4] = {0.f, 0.f, 0.f, 0.f};

    for (int nt = 0; nt < Hn / BN; ++nt) {
        const int n0 = nt * BN;
        float acc[4][4];
#pragma unroll
        for (int i = 0; i < 4; ++i)
#pragma unroll
            for (int j = 0; j < 4; ++j) acc[i][j] = 0.f;

        for (int k0 = 0; k0 < En; k0 += BK) {
            __syncthreads();
            {
                const float4 a = *(const float4*)(enc + (size_t)(m0 + lrow) * En + k0 + lcg);
                As[lcg + 0][lrow] = a.x;
                As[lcg + 1][lrow] = a.y;
                As[lcg + 2][lrow] = a.z;
                As[lcg + 3][lrow] = a.w;
                const float4 w = *(const float4*)(Mw + (size_t)(n0 + lrow) * (En + Hn) + k0 + lcg);
                Bs[lcg + 0][lrow] = w.x;
                Bs[lcg + 1][lrow] = w.y;
                Bs[lcg + 2][lrow] = w.z;
                Bs[lcg + 3][lrow] = w.w;
            }
            __syncthreads();

#pragma unroll
            for (int k = 0; k < BK; ++k) {
                const float4 am = *(const float4*)&As[k][ty * 4];
                const float4 bn = *(const float4*)&Bs[k][tx * 4];
                float rm[4] = {am.x, am.y, am.z, am.w};
                float rn[4] = {bn.x, bn.y, bn.z, bn.w};
#pragma unroll
                for (int i = 0; i < 4; ++i)
#pragma unroll
                    for (int j = 0; j < 4; ++j)
                        acc[i][j] = fmaf(rm[i], rn[j], acc[i][j]);
            }
        }

        // epilogue: tanh + V-weighted reduce over this n-tile
#pragma unroll
        for (int j = 0; j < 4; ++j) {
            const int n = n0 + tx * 4 + j;
            const float c = g_hidc[b * Hn + n];
            const float v = Vw[n];
#pragma unroll
            for (int i = 0; i < 4; ++i)
                rowsum[i] += tanhf(acc[i][j] + c) * v;
        }
    }

    const float vb = Vb[0];
#pragma unroll
    for (int i = 0; i < 4; ++i) {
        float r = rowsum[i];
#pragma unroll
        for (int o = 8; o; o >>= 1)
            r += __shfl_xor_sync(0xffffffffu, r, o, 16);
        if (tx == 0) g_scores[m0 + ty * 4 + i] = r + vb;
    }
}

// ---------------------------------------------------------------------------
// Kernel 3: masked softmax over S per batch row. mask != 0 -> -1e30.
// NOTE: mask arrives as int32 (bool upcast by harness), NOT bytes.
// ---------------------------------------------------------------------------
__global__ void softmax_kernel(const int* __restrict__ mask,
                               float* __restrict__ weights /* B*S */) {
    const int b = blockIdx.x;
    const int tid = threadIdx.x;
    __shared__ float red[256];

    float vals[8];
    float mx = -INFINITY;
#pragma unroll
    for (int i = 0; i < 8; ++i) {
        const int s = tid + i * 256;
        float sc = g_scores[b * Sn + s];
        if (mask[b * Sn + s] != 0) sc = -1e30f;
        vals[i] = sc;
        mx = fmaxf(mx, sc);
    }
    red[tid] = mx;
    __syncthreads();
    for (int o = 128; o; o >>= 1) {
        if (tid < o) red[tid] = fmaxf(red[tid], red[tid + o]);
        __syncthreads();
    }
    mx = red[0];
    __syncthreads();

    float sum = 0.f;
#pragma unroll
    for (int i = 0; i < 8; ++i) {
        vals[i] = __expf(vals[i] - mx);
        sum += vals[i];
    }
    red[tid] = sum;
    __syncthreads();
    for (int o = 128; o; o >>= 1) {
        if (tid < o) red[tid] += red[tid + o];
        __syncthreads();
    }
    const float inv = 1.0f / red[0];
#pragma unroll
    for (int i = 0; i < 8; ++i)
        weights[b * Sn + tid + i * 256] = vals[i] * inv;
}

// ---------------------------------------------------------------------------
// Kernel 4: weighted[b,e] = sum_s weights[b,s] * enc[b,s,e]
// ---------------------------------------------------------------------------
__global__ void weighted_kernel(const float* __restrict__ enc,
                                const float* __restrict__ weights,
                                float* __restrict__ out /* B*E */) {
    const int b = blockIdx.y;
    const int e = blockIdx.x * 256 + threadIdx.x;
    const int s0 = blockIdx.z * 256;

    __shared__ float w[256];
    w[threadIdx.x] = weights[b * Sn + s0 + threadIdx.x];
    __syncthreads();

    const float* ep = enc + (size_t)b * Sn * En + (size_t)s0 * En + e;
    float acc = 0.f;
#pragma unroll 8
    for (int s = 0; s < 256; ++s)
        acc = fmaf(w[s], ep[(size_t)s * En], acc);
    atomicAdd(&out[b * En + e], acc);
}

// ---------------------------------------------------------------------------
extern "C" void kernel_launch(void* const* d_in, const int* in_sizes, int n_in,
                              void* d_out, int out_size) {
    const float* hidden = (const float*)d_in[0];
    const float* enc    = (const float*)d_in[1];
    const int*   mask   = (const int*)d_in[2];      // int32, not bytes!
    const float* Mw     = (const float*)d_in[3];
    const float* Mb     = (const float*)d_in[4];
    const float* Vw     = (const float*)d_in[5];
    const float* Vb     = (const float*)d_in[6];

    float* out_weighted = (float*)d_out;            // B*E floats
    float* out_weights  = (float*)d_out + Bn * En;  // B*S floats

    zero_out_kernel<<<(Bn * En + 255) / 256, 256>>>(out_weighted, Bn * En);
    colsum_kernel<<<Hn / 256, 256>>>(Mw);
    hidc_kernel<<<(Bn * Hn) / 256, 256>>>(hidden, Mb);
    scores_kernel<<<(Bn * Sn) / BM, 256>>>(enc, Mw, Vw, Vb);
    softmax_kernel<<<Bn, 256>>>(mask, out_weights);

    dim3 wgrid(En / 256, Bn, Sn / 256);
    weighted_kernel<<<wgrid, 256>>>(enc, out_weights, out_weighted);
}

// round 6
// speedup vs baseline: 2.6730x; 2.6730x over previous
#include <cuda_runtime.h>
#include <cuda_bf16.h>
#include <cstdint>
#include <math.h>

#define Bn 32
#define Sn 2048
#define En 1024
#define Hn 1024

// -------------------- device scratch (no cudaMalloc allowed) ----------------
__device__ __nv_bfloat16 g_ench[(size_t)Bn * Sn * En];  // bf16 hi of enc
__device__ __nv_bfloat16 g_encl[(size_t)Bn * Sn * En];  // bf16 lo (residual)
__device__ __nv_bfloat16 g_mwh[Hn * En];                // bf16 hi of M_w[:, :E]
__device__ __nv_bfloat16 g_mwl[Hn * En];                // bf16 lo (residual)
__device__ float g_colsum[Hn];
__device__ float g_hidc[Bn * Hn];
__device__ float g_scores[Bn * Sn];

// -------------------- helpers ------------------------------------------------
__device__ __forceinline__ uint32_t smem_u32(const void* p) {
    return (uint32_t)__cvta_generic_to_shared(const_cast<void*>(p));
}
__device__ __forceinline__ void cpasync16(uint32_t dst, const void* src) {
    asm volatile("cp.async.cg.shared.global [%0], [%1], 16;" :: "r"(dst), "l"(src));
}
#define CP_COMMIT() asm volatile("cp.async.commit_group;" ::: "memory")
#define CP_WAIT(n)  asm volatile("cp.async.wait_group %0;" :: "n"(n) : "memory")

__device__ __forceinline__ void ldsm4(uint32_t* r, uint32_t addr) {
    asm volatile("ldmatrix.sync.aligned.m8n8.x4.shared.b16 {%0,%1,%2,%3}, [%4];"
                 : "=r"(r[0]), "=r"(r[1]), "=r"(r[2]), "=r"(r[3]) : "r"(addr));
}
__device__ __forceinline__ void mma_16816(float* c, const uint32_t* a, const uint32_t* b) {
    asm volatile(
        "mma.sync.aligned.m16n8k16.row.col.f32.bf16.bf16.f32 "
        "{%0,%1,%2,%3}, {%4,%5,%6,%7}, {%8,%9}, {%0,%1,%2,%3};"
        : "+f"(c[0]), "+f"(c[1]), "+f"(c[2]), "+f"(c[3])
        : "r"(a[0]), "r"(a[1]), "r"(a[2]), "r"(a[3]), "r"(b[0]), "r"(b[1]));
}
// tanh via ex2/rcp: ~1e-6 abs error, 4 instructions
__device__ __forceinline__ float tanh_fast(float x) {
    float e;
    asm("ex2.approx.f32 %0, %1;" : "=f"(e) : "f"(x * 2.885390082f)); // 2*log2(e)
    float r;
    asm("rcp.approx.f32 %0, %1;" : "=f"(r) : "f"(e + 1.0f));
    return fmaf(-2.0f, r, 1.0f);
}
#define SW128(o) ((o) ^ ((((uint32_t)(o)) >> 3) & 0x70u))

// -------------------- trivial prep kernels ----------------------------------
__global__ void zero_out_kernel(float* __restrict__ out, int n) {
    int i = blockIdx.x * blockDim.x + threadIdx.x;
    if (i < n) out[i] = 0.0f;
}
__global__ void colsum_kernel(const float* __restrict__ Mw) {
    const int h = blockIdx.x * blockDim.x + threadIdx.x;
    if (h >= Hn) return;
    const float* p = Mw + En + h;
    float acc = 0.0f;
#pragma unroll 8
    for (int g = 0; g < Hn; ++g) acc += p[(size_t)g * (En + Hn)];
    g_colsum[h] = acc;
}
__global__ void hidc_kernel(const float* __restrict__ hidden, const float* __restrict__ Mb) {
    const int i = blockIdx.x * blockDim.x + threadIdx.x;
    if (i >= Bn * Hn) return;
    const int h = i & (Hn - 1);
    g_hidc[i] = fmaf(hidden[i], g_colsum[h], Mb[h]);
}
__global__ void mwconv_kernel(const float* __restrict__ Mw) {
    const int i = blockIdx.x * blockDim.x + threadIdx.x;
    if (i >= Hn * En) return;
    const int h = i >> 10, e = i & 1023;
    const float x = Mw[(size_t)h * (En + Hn) + e];
    const __nv_bfloat16 hi = __float2bfloat16(x);
    g_mwh[i] = hi;
    g_mwl[i] = __float2bfloat16(x - __bfloat162float(hi));
}
__global__ void encconv_kernel(const float* __restrict__ enc) {
    const size_t i4 = ((size_t)blockIdx.x * blockDim.x + threadIdx.x) * 4;
    const float4 v = *(const float4*)(enc + i4);
    __nv_bfloat162 h0 = __floats2bfloat162_rn(v.x, v.y);
    __nv_bfloat162 h1 = __floats2bfloat162_rn(v.z, v.w);
    __nv_bfloat162 l0 = __floats2bfloat162_rn(v.x - __bfloat162float(h0.x),
                                              v.y - __bfloat162float(h0.y));
    __nv_bfloat162 l1 = __floats2bfloat162_rn(v.z - __bfloat162float(h1.x),
                                              v.w - __bfloat162float(h1.y));
    *(__nv_bfloat162*)(g_ench + i4)     = h0;
    *(__nv_bfloat162*)(g_ench + i4 + 2) = h1;
    *(__nv_bfloat162*)(g_encl + i4)     = l0;
    *(__nv_bfloat162*)(g_encl + i4 + 2) = l1;
}

// -------------------- mma.sync fused scores kernel ---------------------------
// grid = 512 (m-tiles of 128 rows of B*S), 256 threads = 8 warps (4m x 2n).
// Per CTA: nt 0..7 (BN=128 of H), kt 0..15 (BK=64 of E).
// C = Ah.Bh^T + Al.Bh^T + Ah.Bl^T  (fp32 accum, bf16 operands)
// per-nt epilogue: rowsum += tanh(C + hidc) . Vw  (in registers)
#define BM 128
#define BN 128
#define BK 64
#define NT (Hn / BN)        // 8
#define KT (En / BK)        // 16
#define NITER (NT * KT)     // 128
#define STAGE_BYTES 65536
#define T_AH 0
#define T_AL 16384
#define T_BH 32768
#define T_BL 49152
#define OFF_VW  (2 * STAGE_BYTES)
#define OFF_HC  (OFF_VW + 4096)
#define OFF_RED (OFF_HC + 4096)
#define SMEM_SC (OFF_RED + 512)

__device__ __forceinline__ void load_stage(uint32_t sb, int stage, int nt, int kt,
                                           int m0, int tid) {
    const int r  = tid >> 1;
    const int cb = (tid & 1) * 64;                  // byte offset within 128B row
    const uint32_t sbase = sb + stage * STAGE_BYTES;
    const uint32_t soff = (uint32_t)(r * 128 + cb);
    const char* ah = (const char*)(g_ench + (size_t)(m0 + r) * En + kt * BK) + cb;
    const char* al = (const char*)(g_encl + (size_t)(m0 + r) * En + kt * BK) + cb;
    const char* bh = (const char*)(g_mwh + (size_t)(nt * BN + r) * En + kt * BK) + cb;
    const char* bl = (const char*)(g_mwl + (size_t)(nt * BN + r) * En + kt * BK) + cb;
#pragma unroll
    for (int i = 0; i < 4; ++i) {
        const uint32_t d = SW128(soff + i * 16);
        cpasync16(sbase + T_AH + d, ah + i * 16);
        cpasync16(sbase + T_AL + d, al + i * 16);
        cpasync16(sbase + T_BH + d, bh + i * 16);
        cpasync16(sbase + T_BL + d, bl + i * 16);
    }
}

__global__ __launch_bounds__(256, 1)
void scores_mma_kernel(const float* __restrict__ Vw,
                       const float* __restrict__ Vb) {
    extern __shared__ char smem[];
    const uint32_t sb = smem_u32(smem);
    const int tid = threadIdx.x, wid = tid >> 5, lid = tid & 31;
    const int wm = wid & 3, wn = wid >> 2;
    const int m0 = blockIdx.x * BM;
    const int b = m0 / Sn;

    // preload Vw and this batch's hidc into smem
    float* s_vw = (float*)(smem + OFF_VW);
    float* s_hc = (float*)(smem + OFF_HC);
    for (int i = tid; i < Hn; i += 256) {
        s_vw[i] = Vw[i];
        s_hc[i] = g_hidc[b * Hn + i];
    }

    // ldmatrix lane geometry
    const int a_row = wm * 32 + (lid & 15);
    const int a_kb  = (lid >> 4) * 16;
    const int b_row = wn * 64 + (lid & 7) + ((lid >> 4) << 3);
    const int b_kb  = ((lid >> 3) & 1) * 16;

    float c[2][8][4];
#pragma unroll
    for (int mi = 0; mi < 2; ++mi)
#pragma unroll
        for (int j = 0; j < 8; ++j)
#pragma unroll
            for (int v = 0; v < 4; ++v) c[mi][j][v] = 0.0f;
    float rs[4] = {0.f, 0.f, 0.f, 0.f};

    load_stage(sb, 0, 0, 0, m0, tid);
    CP_COMMIT();

    for (int t = 0; t < NITER; ++t) {
        const int s = t & 1;
        if (t + 1 < NITER) {
            load_stage(sb, s ^ 1, (t + 1) >> 4, (t + 1) & 15, m0, tid);
            CP_COMMIT();
            CP_WAIT(1);
        } else {
            CP_WAIT(0);
        }
        __syncthreads();

        const uint32_t sbase = sb + s * STAGE_BYTES;
#pragma unroll
        for (int ks = 0; ks < 4; ++ks) {
            const int kb = ks * 32;
            uint32_t ah[2][4], al[2][4], bh[4][4], bl[4][4];
#pragma unroll
            for (int mi = 0; mi < 2; ++mi) {
                const uint32_t ao = SW128((uint32_t)((a_row + mi * 16) * 128 + a_kb + kb));
                ldsm4(ah[mi], sbase + T_AH + ao);
                ldsm4(al[mi], sbase + T_AL + ao);
            }
#pragma unroll
            for (int q = 0; q < 4; ++q) {
                const uint32_t bo = SW128((uint32_t)((b_row + q * 16) * 128 + b_kb + kb));
                ldsm4(bh[q], sbase + T_BH + bo);
                ldsm4(bl[q], sbase + T_BL + bo);
            }
#pragma unroll
            for (int mi = 0; mi < 2; ++mi)
#pragma unroll
                for (int q = 0; q < 4; ++q) {
                    mma_16816(c[mi][2 * q],     ah[mi], &bh[q][0]);
                    mma_16816(c[mi][2 * q + 1], ah[mi], &bh[q][2]);
                    mma_16816(c[mi][2 * q],     al[mi], &bh[q][0]);
                    mma_16816(c[mi][2 * q + 1], al[mi], &bh[q][2]);
                    mma_16816(c[mi][2 * q],     ah[mi], &bl[q][0]);
                    mma_16816(c[mi][2 * q + 1], ah[mi], &bl[q][2]);
                }
        }

        if ((t & (KT - 1)) == (KT - 1)) {
            // epilogue for n-tile nt = t >> 4: tanh + V-weighted reduce
            const int nt = t >> 4;
            const int nb = nt * BN + wn * 64 + (lid & 3) * 2;
#pragma unroll
            for (int mi = 0; mi < 2; ++mi)
#pragma unroll
                for (int j = 0; j < 8; ++j) {
                    const int n = nb + j * 8;
                    const float hc0 = s_hc[n],     vw0 = s_vw[n];
                    const float hc1 = s_hc[n + 1], vw1 = s_vw[n + 1];
                    float* cc = c[mi][j];
                    rs[mi * 2 + 0] = fmaf(tanh_fast(cc[0] + hc0), vw0,
                                     fmaf(tanh_fast(cc[1] + hc1), vw1, rs[mi * 2 + 0]));
                    rs[mi * 2 + 1] = fmaf(tanh_fast(cc[2] + hc0), vw0,
                                     fmaf(tanh_fast(cc[3] + hc1), vw1, rs[mi * 2 + 1]));
                    cc[0] = cc[1] = cc[2] = cc[3] = 0.0f;
                }
        }
        __syncthreads();
    }

    // reduce rowsums across the 4 lanes sharing each row
#pragma unroll
    for (int i = 0; i < 4; ++i) {
        rs[i] += __shfl_xor_sync(0xffffffffu, rs[i], 1);
        rs[i] += __shfl_xor_sync(0xffffffffu, rs[i], 2);
    }
    float* red = (float*)(smem + OFF_RED);
    const int r0 = wm * 32 + (lid >> 2);
    if ((lid & 3) == 0 && wn == 0) {
        red[r0]      = rs[0];
        red[r0 + 8]  = rs[1];
        red[r0 + 16] = rs[2];
        red[r0 + 24] = rs[3];
    }
    __syncthreads();
    if ((lid & 3) == 0 && wn == 1) {
        const float vb = Vb[0];
        g_scores[m0 + r0]      = red[r0]      + rs[0] + vb;
        g_scores[m0 + r0 + 8]  = red[r0 + 8]  + rs[1] + vb;
        g_scores[m0 + r0 + 16] = red[r0 + 16] + rs[2] + vb;
        g_scores[m0 + r0 + 24] = red[r0 + 24] + rs[3] + vb;
    }
}

// -------------------- softmax (mask as int32) --------------------------------
__global__ void softmax_kernel(const int* __restrict__ mask,
                               float* __restrict__ weights) {
    const int b = blockIdx.x;
    const int tid = threadIdx.x;
    __shared__ float red[256];

    float vals[8];
    float mx = -INFINITY;
#pragma unroll
    for (int i = 0; i < 8; ++i) {
        const int s = tid + i * 256;
        float sc = g_scores[b * Sn + s];
        if (mask[b * Sn + s] != 0) sc = -1e30f;
        vals[i] = sc;
        mx = fmaxf(mx, sc);
    }
    red[tid] = mx;
    __syncthreads();
    for (int o = 128; o; o >>= 1) {
        if (tid < o) red[tid] = fmaxf(red[tid], red[tid + o]);
        __syncthreads();
    }
    mx = red[0];
    __syncthreads();

    float sum = 0.f;
#pragma unroll
    for (int i = 0; i < 8; ++i) {
        vals[i] = __expf(vals[i] - mx);
        sum += vals[i];
    }
    red[tid] = sum;
    __syncthreads();
    for (int o = 128; o; o >>= 1) {
        if (tid < o) red[tid] += red[tid + o];
        __syncthreads();
    }
    const float inv = 1.0f / red[0];
#pragma unroll
    for (int i = 0; i < 8; ++i)
        weights[b * Sn + tid + i * 256] = vals[i] * inv;
}

// -------------------- weighted sum -------------------------------------------
__global__ void weighted_kernel(const float* __restrict__ enc,
                                const float* __restrict__ weights,
                                float* __restrict__ out) {
    const int b = blockIdx.y;
    const int e = blockIdx.x * 256 + threadIdx.x;
    const int s0 = blockIdx.z * 256;

    __shared__ float w[256];
    w[threadIdx.x] = weights[b * Sn + s0 + threadIdx.x];
    __syncthreads();

    const float* ep = enc + (size_t)b * Sn * En + (size_t)s0 * En + e;
    float acc = 0.f;
#pragma unroll 8
    for (int s = 0; s < 256; ++s)
        acc = fmaf(w[s], ep[(size_t)s * En], acc);
    atomicAdd(&out[b * En + e], acc);
}

// -----------------------------------------------------------------------------
extern "C" void kernel_launch(void* const* d_in, const int* in_sizes, int n_in,
                              void* d_out, int out_size) {
    const float* hidden = (const float*)d_in[0];
    const float* enc    = (const float*)d_in[1];
    const int*   mask   = (const int*)d_in[2];
    const float* Mw     = (const float*)d_in[3];
    const float* Mb     = (const float*)d_in[4];
    const float* Vw     = (const float*)d_in[5];
    const float* Vb     = (const float*)d_in[6];

    float* out_weighted = (float*)d_out;
    float* out_weights  = (float*)d_out + Bn * En;

    cudaFuncSetAttribute(scores_mma_kernel,
                         cudaFuncAttributeMaxDynamicSharedMemorySize, SMEM_SC);

    zero_out_kernel<<<(Bn * En + 255) / 256, 256>>>(out_weighted, Bn * En);
    colsum_kernel<<<Hn / 256, 256>>>(Mw);
    hidc_kernel<<<(Bn * Hn) / 256, 256>>>(hidden, Mb);
    mwconv_kernel<<<(Hn * En) / 256, 256>>>(Mw);
    encconv_kernel<<<((size_t)Bn * Sn * En / 4) / 256, 256>>>(enc);

    scores_mma_kernel<<<(Bn * Sn) / BM, 256, SMEM_SC>>>(Vw, Vb);

    softmax_kernel<<<Bn, 256>>>(mask, out_weights);

    dim3 wgrid(En / 256, Bn, Sn / 256);
    weighted_kernel<<<wgrid, 256>>>(enc, out_weights, out_weighted);
}

// round 7
// speedup vs baseline: 5.2126x; 1.9501x over previous
#include <cuda_runtime.h>
#include <cuda_bf16.h>
#include <cstdint>
#include <math.h>

#define Bn 32
#define Sn 2048
#define En 1024
#define Hn 1024

// -------------------- device scratch (no cudaMalloc allowed) ----------------
__device__ __nv_bfloat16 g_ench[(size_t)Bn * Sn * En];  // bf16 of enc
__device__ __nv_bfloat16 g_mwh[Hn * En];                // bf16 of M_w[:, :E]
__device__ float g_colsum[Hn];
__device__ float g_hidc[Bn * Hn];
__device__ float g_scores[Bn * Sn];

// -------------------- helpers ------------------------------------------------
__device__ __forceinline__ uint32_t smem_u32(const void* p) {
    return (uint32_t)__cvta_generic_to_shared(const_cast<void*>(p));
}
__device__ __forceinline__ void cpasync16(uint32_t dst, const void* src) {
    asm volatile("cp.async.cg.shared.global [%0], [%1], 16;" :: "r"(dst), "l"(src));
}
#define CP_COMMIT() asm volatile("cp.async.commit_group;" ::: "memory")
#define CP_WAIT(n)  asm volatile("cp.async.wait_group %0;" :: "n"(n) : "memory")

__device__ __forceinline__ void ldsm4(uint32_t* r, uint32_t addr) {
    asm volatile("ldmatrix.sync.aligned.m8n8.x4.shared.b16 {%0,%1,%2,%3}, [%4];"
                 : "=r"(r[0]), "=r"(r[1]), "=r"(r[2]), "=r"(r[3]) : "r"(addr));
}
__device__ __forceinline__ void mma_16816(float* c, const uint32_t* a, const uint32_t* b) {
    asm volatile(
        "mma.sync.aligned.m16n8k16.row.col.f32.bf16.bf16.f32 "
        "{%0,%1,%2,%3}, {%4,%5,%6,%7}, {%8,%9}, {%0,%1,%2,%3};"
        : "+f"(c[0]), "+f"(c[1]), "+f"(c[2]), "+f"(c[3])
        : "r"(a[0]), "r"(a[1]), "r"(a[2]), "r"(a[3]), "r"(b[0]), "r"(b[1]));
}
// tanh via ex2/rcp: ~1e-6 abs error
__device__ __forceinline__ float tanh_fast(float x) {
    float e;
    asm("ex2.approx.f32 %0, %1;" : "=f"(e) : "f"(x * 2.885390082f)); // 2*log2(e)
    float r;
    asm("rcp.approx.f32 %0, %1;" : "=f"(r) : "f"(e + 1.0f));
    return fmaf(-2.0f, r, 1.0f);
}
#define SW128(o) ((o) ^ ((((uint32_t)(o)) >> 3) & 0x70u))

// -------------------- trivial prep kernels ----------------------------------
__global__ void zero_out_kernel(float* __restrict__ out, int n) {
    int i = blockIdx.x * blockDim.x + threadIdx.x;
    if (i < n) out[i] = 0.0f;
}
__global__ void colsum_kernel(const float* __restrict__ Mw) {
    const int h = blockIdx.x * blockDim.x + threadIdx.x;
    if (h >= Hn) return;
    const float* p = Mw + En + h;
    float acc = 0.0f;
#pragma unroll 8
    for (int g = 0; g < Hn; ++g) acc += p[(size_t)g * (En + Hn)];
    g_colsum[h] = acc;
}
__global__ void hidc_kernel(const float* __restrict__ hidden, const float* __restrict__ Mb) {
    const int i = blockIdx.x * blockDim.x + threadIdx.x;
    if (i >= Bn * Hn) return;
    const int h = i & (Hn - 1);
    g_hidc[i] = fmaf(hidden[i], g_colsum[h], Mb[h]);
}
__global__ void mwconv_kernel(const float* __restrict__ Mw) {
    const int i = blockIdx.x * blockDim.x + threadIdx.x;
    if (i >= Hn * En) return;
    const int h = i >> 10, e = i & 1023;
    g_mwh[i] = __float2bfloat16(Mw[(size_t)h * (En + Hn) + e]);
}
__global__ void encconv_kernel(const float* __restrict__ enc) {
    const size_t i4 = ((size_t)blockIdx.x * blockDim.x + threadIdx.x) * 4;
    const float4 v = *(const float4*)(enc + i4);
    *(__nv_bfloat162*)(g_ench + i4)     = __floats2bfloat162_rn(v.x, v.y);
    *(__nv_bfloat162*)(g_ench + i4 + 2) = __floats2bfloat162_rn(v.z, v.w);
}

// -------------------- mma.sync fused scores kernel ---------------------------
// grid = 512 (m-tiles of 128 rows of B*S), 256 threads = 8 warps (4m x 2n).
// Per CTA: nt 0..7 (BN=128 of H), kt 0..15 (BK=64 of E).
// C = A.B^T  (bf16 operands, fp32 accum, single term)
// per-nt epilogue: rowsum += tanh(C + hidc) . Vw  (in registers)
#define BM 128
#define BN 128
#define BK 64
#define NT (Hn / BN)        // 8
#define KT (En / BK)        // 16
#define NITER (NT * KT)     // 128
#define STAGE_BYTES 32768
#define T_A 0
#define T_B 16384
#define OFF_VW  (2 * STAGE_BYTES)
#define OFF_HC  (OFF_VW + 4096)
#define OFF_RED (OFF_HC + 4096)
#define SMEM_SC (OFF_RED + 512)

__device__ __forceinline__ void load_stage(uint32_t sb, int stage, int nt, int kt,
                                           int m0, int tid) {
    const int r  = tid >> 1;
    const int cb = (tid & 1) * 64;                  // byte offset within 128B row
    const uint32_t sbase = sb + stage * STAGE_BYTES;
    const uint32_t soff = (uint32_t)(r * 128 + cb);
    const char* a = (const char*)(g_ench + (size_t)(m0 + r) * En + kt * BK) + cb;
    const char* b = (const char*)(g_mwh + (size_t)(nt * BN + r) * En + kt * BK) + cb;
#pragma unroll
    for (int i = 0; i < 4; ++i) {
        const uint32_t d = SW128(soff + i * 16);
        cpasync16(sbase + T_A + d, a + i * 16);
        cpasync16(sbase + T_B + d, b + i * 16);
    }
}

__global__ __launch_bounds__(256, 1)
void scores_mma_kernel(const float* __restrict__ Vw,
                       const float* __restrict__ Vb) {
    extern __shared__ char smem[];
    const uint32_t sb = smem_u32(smem);
    const int tid = threadIdx.x, wid = tid >> 5, lid = tid & 31;
    const int wm = wid & 3, wn = wid >> 2;
    const int m0 = blockIdx.x * BM;
    const int b = m0 / Sn;

    // preload Vw and this batch's hidc into smem
    float* s_vw = (float*)(smem + OFF_VW);
    float* s_hc = (float*)(smem + OFF_HC);
    for (int i = tid; i < Hn; i += 256) {
        s_vw[i] = Vw[i];
        s_hc[i] = g_hidc[b * Hn + i];
    }

    // ldmatrix lane geometry
    const int a_row = wm * 32 + (lid & 15);
    const int a_kb  = (lid >> 4) * 16;
    const int b_row = wn * 64 + (lid & 7) + ((lid >> 4) << 3);
    const int b_kb  = ((lid >> 3) & 1) * 16;

    float c[2][8][4];
#pragma unroll
    for (int mi = 0; mi < 2; ++mi)
#pragma unroll
        for (int j = 0; j < 8; ++j)
#pragma unroll
            for (int v = 0; v < 4; ++v) c[mi][j][v] = 0.0f;
    float rs[4] = {0.f, 0.f, 0.f, 0.f};

    load_stage(sb, 0, 0, 0, m0, tid);
    CP_COMMIT();

    for (int t = 0; t < NITER; ++t) {
        const int s = t & 1;
        if (t + 1 < NITER) {
            load_stage(sb, s ^ 1, (t + 1) >> 4, (t + 1) & 15, m0, tid);
            CP_COMMIT();
            CP_WAIT(1);
        } else {
            CP_WAIT(0);
        }
        __syncthreads();

        const uint32_t sbase = sb + s * STAGE_BYTES;
#pragma unroll
        for (int ks = 0; ks < 4; ++ks) {
            const int kb = ks * 32;
            uint32_t ah[2][4], bh[4][4];
#pragma unroll
            for (int mi = 0; mi < 2; ++mi) {
                const uint32_t ao = SW128((uint32_t)((a_row + mi * 16) * 128 + a_kb + kb));
                ldsm4(ah[mi], sbase + T_A + ao);
            }
#pragma unroll
            for (int q = 0; q < 4; ++q) {
                const uint32_t bo = SW128((uint32_t)((b_row + q * 16) * 128 + b_kb + kb));
                ldsm4(bh[q], sbase + T_B + bo);
            }
#pragma unroll
            for (int mi = 0; mi < 2; ++mi)
#pragma unroll
                for (int q = 0; q < 4; ++q) {
                    mma_16816(c[mi][2 * q],     ah[mi], &bh[q][0]);
                    mma_16816(c[mi][2 * q + 1], ah[mi], &bh[q][2]);
                }
        }

        if ((t & (KT - 1)) == (KT - 1)) {
            // epilogue for n-tile nt = t >> 4: tanh + V-weighted reduce
            const int nt = t >> 4;
            const int nb = nt * BN + wn * 64 + (lid & 3) * 2;
#pragma unroll
            for (int mi = 0; mi < 2; ++mi)
#pragma unroll
                for (int j = 0; j < 8; ++j) {
                    const int n = nb + j * 8;
                    const float hc0 = s_hc[n],     vw0 = s_vw[n];
                    const float hc1 = s_hc[n + 1], vw1 = s_vw[n + 1];
                    float* cc = c[mi][j];
                    rs[mi * 2 + 0] = fmaf(tanh_fast(cc[0] + hc0), vw0,
                                     fmaf(tanh_fast(cc[1] + hc1), vw1, rs[mi * 2 + 0]));
                    rs[mi * 2 + 1] = fmaf(tanh_fast(cc[2] + hc0), vw0,
                                     fmaf(tanh_fast(cc[3] + hc1), vw1, rs[mi * 2 + 1]));
                    cc[0] = cc[1] = cc[2] = cc[3] = 0.0f;
                }
        }
        __syncthreads();
    }

    // reduce rowsums across the 4 lanes sharing each row
#pragma unroll
    for (int i = 0; i < 4; ++i) {
        rs[i] += __shfl_xor_sync(0xffffffffu, rs[i], 1);
        rs[i] += __shfl_xor_sync(0xffffffffu, rs[i], 2);
    }
    float* red = (float*)(smem + OFF_RED);
    const int r0 = wm * 32 + (lid >> 2);
    if ((lid & 3) == 0 && wn == 0) {
        red[r0]      = rs[0];
        red[r0 + 8]  = rs[1];
        red[r0 + 16] = rs[2];
        red[r0 + 24] = rs[3];
    }
    __syncthreads();
    if ((lid & 3) == 0 && wn == 1) {
        const float vb = Vb[0];
        g_scores[m0 + r0]      = red[r0]      + rs[0] + vb;
        g_scores[m0 + r0 + 8]  = red[r0 + 8]  + rs[1] + vb;
        g_scores[m0 + r0 + 16] = red[r0 + 16] + rs[2] + vb;
        g_scores[m0 + r0 + 24] = red[r0 + 24] + rs[3] + vb;
    }
}

// -------------------- softmax (mask as int32) --------------------------------
__global__ void softmax_kernel(const int* __restrict__ mask,
                               float* __restrict__ weights) {
    const int b = blockIdx.x;
    const int tid = threadIdx.x;
    __shared__ float red[256];

    float vals[8];
    float mx = -INFINITY;
#pragma unroll
    for (int i = 0; i < 8; ++i) {
        const int s = tid + i * 256;
        float sc = g_scores[b * Sn + s];
        if (mask[b * Sn + s] != 0) sc = -1e30f;
        vals[i] = sc;
        mx = fmaxf(mx, sc);
    }
    red[tid] = mx;
    __syncthreads();
    for (int o = 128; o; o >>= 1) {
        if (tid < o) red[tid] = fmaxf(red[tid], red[tid + o]);
        __syncthreads();
    }
    mx = red[0];
    __syncthreads();

    float sum = 0.f;
#pragma unroll
    for (int i = 0; i < 8; ++i) {
        vals[i] = __expf(vals[i] - mx);
        sum += vals[i];
    }
    red[tid] = sum;
    __syncthreads();
    for (int o = 128; o; o >>= 1) {
        if (tid < o) red[tid] += red[tid + o];
        __syncthreads();
    }
    const float inv = 1.0f / red[0];
#pragma unroll
    for (int i = 0; i < 8; ++i)
        weights[b * Sn + tid + i * 256] = vals[i] * inv;
}

// -------------------- weighted sum (fp32 enc for accuracy) -------------------
__global__ void weighted_kernel(const float* __restrict__ enc,
                                const float* __restrict__ weights,
                                float* __restrict__ out) {
    const int b = blockIdx.y;
    const int e = blockIdx.x * 256 + threadIdx.x;
    const int s0 = blockIdx.z * 256;

    __shared__ float w[256];
    w[threadIdx.x] = weights[b * Sn + s0 + threadIdx.x];
    __syncthreads();

    const float* ep = enc + (size_t)b * Sn * En + (size_t)s0 * En + e;
    float acc = 0.f;
#pragma unroll 8
    for (int s = 0; s < 256; ++s)
        acc = fmaf(w[s], ep[(size_t)s * En], acc);
    atomicAdd(&out[b * En + e], acc);
}

// -----------------------------------------------------------------------------
extern "C" void kernel_launch(void* const* d_in, const int* in_sizes, int n_in,
                              void* d_out, int out_size) {
    const float* hidden = (const float*)d_in[0];
    const float* enc    = (const float*)d_in[1];
    const int*   mask   = (const int*)d_in[2];
    const float* Mw     = (const float*)d_in[3];
    const float* Mb     = (const float*)d_in[4];
    const float* Vw     = (const float*)d_in[5];
    const float* Vb     = (const float*)d_in[6];

    float* out_weighted = (float*)d_out;
    float* out_weights  = (float*)d_out + Bn * En;

    cudaFuncSetAttribute(scores_mma_kernel,
                         cudaFuncAttributeMaxDynamicSharedMemorySize, SMEM_SC);

    zero_out_kernel<<<(Bn * En + 255) / 256, 256>>>(out_weighted, Bn * En);
    colsum_kernel<<<Hn / 256, 256>>>(Mw);
    hidc_kernel<<<(Bn * Hn) / 256, 256>>>(hidden, Mb);
    mwconv_kernel<<<(Hn * En) / 256, 256>>>(Mw);
    encconv_kernel<<<((size_t)Bn * Sn * En / 4) / 256, 256>>>(enc);

    scores_mma_kernel<<<(Bn * Sn) / BM, 256, SMEM_SC>>>(Vw, Vb);

    softmax_kernel<<<Bn, 256>>>(mask, out_weights);

    dim3 wgrid(En / 256, Bn, Sn / 256);
    weighted_kernel<<<wgrid, 256>>>(enc, out_weights, out_weighted);
}

// round 8
// speedup vs baseline: 6.0079x; 1.1526x over previous
#include <cuda_runtime.h>
#include <cuda_fp16.h>
#include <cstdint>
#include <math.h>

#define Bn 32
#define Sn 2048
#define En 1024
#define Hn 1024

// -------------------- device scratch (no cudaMalloc allowed) ----------------
__device__ __half g_ench[(size_t)Bn * Sn * En];  // fp16 of enc
__device__ __half g_mwh[Hn * En];                // fp16 of M_w[:, :E]
__device__ float g_colsum[Hn];
__device__ float g_hidc[Bn * Hn];
__device__ float g_scores[Bn * Sn];

// -------------------- helpers ------------------------------------------------
__device__ __forceinline__ uint32_t smem_u32(const void* p) {
    return (uint32_t)__cvta_generic_to_shared(const_cast<void*>(p));
}
__device__ __forceinline__ void cpasync16(uint32_t dst, const void* src) {
    asm volatile("cp.async.cg.shared.global [%0], [%1], 16;" :: "r"(dst), "l"(src));
}
#define CP_COMMIT() asm volatile("cp.async.commit_group;" ::: "memory")
#define CP_WAIT(n)  asm volatile("cp.async.wait_group %0;" :: "n"(n) : "memory")

__device__ __forceinline__ void ldsm4(uint32_t* r, uint32_t addr) {
    asm volatile("ldmatrix.sync.aligned.m8n8.x4.shared.b16 {%0,%1,%2,%3}, [%4];"
                 : "=r"(r[0]), "=r"(r[1]), "=r"(r[2]), "=r"(r[3]) : "r"(addr));
}
__device__ __forceinline__ void mma_16816(float* c, const uint32_t* a, const uint32_t* b) {
    asm volatile(
        "mma.sync.aligned.m16n8k16.row.col.f32.f16.f16.f32 "
        "{%0,%1,%2,%3}, {%4,%5,%6,%7}, {%8,%9}, {%0,%1,%2,%3};"
        : "+f"(c[0]), "+f"(c[1]), "+f"(c[2]), "+f"(c[3])
        : "r"(a[0]), "r"(a[1]), "r"(a[2]), "r"(a[3]), "r"(b[0]), "r"(b[1]));
}
// tanh via ex2/rcp: ~1e-6 abs error
__device__ __forceinline__ float tanh_fast(float x) {
    float e;
    asm("ex2.approx.f32 %0, %1;" : "=f"(e) : "f"(x * 2.885390082f)); // 2*log2(e)
    float r;
    asm("rcp.approx.f32 %0, %1;" : "=f"(r) : "f"(e + 1.0f));
    return fmaf(-2.0f, r, 1.0f);
}
#define SW128(o) ((o) ^ ((((uint32_t)(o)) >> 3) & 0x70u))

// -------------------- trivial prep kernels ----------------------------------
__global__ void zero_out_kernel(float* __restrict__ out, int n) {
    int i = blockIdx.x * blockDim.x + threadIdx.x;
    if (i < n) out[i] = 0.0f;
}
__global__ void colsum_kernel(const float* __restrict__ Mw) {
    const int h = blockIdx.x * blockDim.x + threadIdx.x;
    if (h >= Hn) return;
    const float* p = Mw + En + h;
    float acc = 0.0f;
#pragma unroll 8
    for (int g = 0; g < Hn; ++g) acc += p[(size_t)g * (En + Hn)];
    g_colsum[h] = acc;
}
__global__ void hidc_kernel(const float* __restrict__ hidden, const float* __restrict__ Mb) {
    const int i = blockIdx.x * blockDim.x + threadIdx.x;
    if (i >= Bn * Hn) return;
    const int h = i & (Hn - 1);
    g_hidc[i] = fmaf(hidden[i], g_colsum[h], Mb[h]);
}
__global__ void mwconv_kernel(const float* __restrict__ Mw) {
    const int i = blockIdx.x * blockDim.x + threadIdx.x;
    if (i >= Hn * En) return;
    const int h = i >> 10, e = i & 1023;
    g_mwh[i] = __float2half_rn(Mw[(size_t)h * (En + Hn) + e]);
}
__global__ void encconv_kernel(const float* __restrict__ enc) {
    const size_t i4 = ((size_t)blockIdx.x * blockDim.x + threadIdx.x) * 4;
    const float4 v = *(const float4*)(enc + i4);
    __half2 h0 = __floats2half2_rn(v.x, v.y);
    __half2 h1 = __floats2half2_rn(v.z, v.w);
    *(__half2*)(g_ench + i4)     = h0;
    *(__half2*)(g_ench + i4 + 2) = h1;
}

// -------------------- mma.sync fused scores kernel ---------------------------
// grid = 512 (m-tiles of 128 rows of B*S), 256 threads = 8 warps (4m x 2n).
// Per CTA: nt 0..7 (BN=128 of H), kt 0..15 (BK=64 of E).
// C = A.B^T  (fp16 operands, fp32 accum)
// per-nt epilogue: rowsum += tanh(C + hidc) . Vw  (in registers)
// 2 CTAs/SM to hide barrier/epilogue bubbles.
#define BM 128
#define BN 128
#define BK 64
#define NT (Hn / BN)        // 8
#define KT (En / BK)        // 16
#define NITER (NT * KT)     // 128
#define STAGE_BYTES 32768
#define T_A 0
#define T_B 16384
#define OFF_VW  (2 * STAGE_BYTES)
#define OFF_HC  (OFF_VW + 4096)
#define OFF_RED (OFF_HC + 4096)
#define SMEM_SC (OFF_RED + 512)

__device__ __forceinline__ void load_stage(uint32_t sb, int stage, int nt, int kt,
                                           int m0, int tid) {
    const int r  = tid >> 1;
    const int cb = (tid & 1) * 64;                  // byte offset within 128B row
    const uint32_t sbase = sb + stage * STAGE_BYTES;
    const uint32_t soff = (uint32_t)(r * 128 + cb);
    const char* a = (const char*)(g_ench + (size_t)(m0 + r) * En + kt * BK) + cb;
    const char* b = (const char*)(g_mwh + (size_t)(nt * BN + r) * En + kt * BK) + cb;
#pragma unroll
    for (int i = 0; i < 4; ++i) {
        const uint32_t d = SW128(soff + i * 16);
        cpasync16(sbase + T_A + d, a + i * 16);
        cpasync16(sbase + T_B + d, b + i * 16);
    }
}

__global__ __launch_bounds__(256, 2)
void scores_mma_kernel(const float* __restrict__ Vw,
                       const float* __restrict__ Vb) {
    extern __shared__ char smem[];
    const uint32_t sb = smem_u32(smem);
    const int tid = threadIdx.x, wid = tid >> 5, lid = tid & 31;
    const int wm = wid & 3, wn = wid >> 2;
    const int m0 = blockIdx.x * BM;
    const int b = m0 / Sn;

    // preload Vw and this batch's hidc into smem
    float* s_vw = (float*)(smem + OFF_VW);
    float* s_hc = (float*)(smem + OFF_HC);
    for (int i = tid; i < Hn; i += 256) {
        s_vw[i] = Vw[i];
        s_hc[i] = g_hidc[b * Hn + i];
    }

    // ldmatrix lane geometry
    const int a_row = wm * 32 + (lid & 15);
    const int a_kb  = (lid >> 4) * 16;
    const int b_row = wn * 64 + (lid & 7) + ((lid >> 4) << 3);
    const int b_kb  = ((lid >> 3) & 1) * 16;

    float c[2][8][4];
#pragma unroll
    for (int mi = 0; mi < 2; ++mi)
#pragma unroll
        for (int j = 0; j < 8; ++j)
#pragma unroll
            for (int v = 0; v < 4; ++v) c[mi][j][v] = 0.0f;
    float rs[4] = {0.f, 0.f, 0.f, 0.f};

    load_stage(sb, 0, 0, 0, m0, tid);
    CP_COMMIT();

    for (int t = 0; t < NITER; ++t) {
        const int s = t & 1;
        if (t + 1 < NITER) {
            load_stage(sb, s ^ 1, (t + 1) >> 4, (t + 1) & 15, m0, tid);
            CP_COMMIT();
            CP_WAIT(1);
        } else {
            CP_WAIT(0);
        }
        __syncthreads();

        const uint32_t sbase = sb + s * STAGE_BYTES;
#pragma unroll
        for (int ks = 0; ks < 4; ++ks) {
            const int kb = ks * 32;
            uint32_t ah[2][4], bh[4][4];
#pragma unroll
            for (int mi = 0; mi < 2; ++mi) {
                const uint32_t ao = SW128((uint32_t)((a_row + mi * 16) * 128 + a_kb + kb));
                ldsm4(ah[mi], sbase + T_A + ao);
            }
#pragma unroll
            for (int q = 0; q < 4; ++q) {
                const uint32_t bo = SW128((uint32_t)((b_row + q * 16) * 128 + b_kb + kb));
                ldsm4(bh[q], sbase + T_B + bo);
            }
#pragma unroll
            for (int mi = 0; mi < 2; ++mi)
#pragma unroll
                for (int q = 0; q < 4; ++q) {
                    mma_16816(c[mi][2 * q],     ah[mi], &bh[q][0]);
                    mma_16816(c[mi][2 * q + 1], ah[mi], &bh[q][2]);
                }
        }

        if ((t & (KT - 1)) == (KT - 1)) {
            // epilogue for n-tile nt = t >> 4: tanh + V-weighted reduce
            const int nt = t >> 4;
            const int nb = nt * BN + wn * 64 + (lid & 3) * 2;
#pragma unroll
            for (int mi = 0; mi < 2; ++mi)
#pragma unroll
                for (int j = 0; j < 8; ++j) {
                    const int n = nb + j * 8;
                    const float hc0 = s_hc[n],     vw0 = s_vw[n];
                    const float hc1 = s_hc[n + 1], vw1 = s_vw[n + 1];
                    float* cc = c[mi][j];
                    rs[mi * 2 + 0] = fmaf(tanh_fast(cc[0] + hc0), vw0,
                                     fmaf(tanh_fast(cc[1] + hc1), vw1, rs[mi * 2 + 0]));
                    rs[mi * 2 + 1] = fmaf(tanh_fast(cc[2] + hc0), vw0,
                                     fmaf(tanh_fast(cc[3] + hc1), vw1, rs[mi * 2 + 1]));
                    cc[0] = cc[1] = cc[2] = cc[3] = 0.0f;
                }
        }
        __syncthreads();
    }

    // reduce rowsums across the 4 lanes sharing each row
#pragma unroll
    for (int i = 0; i < 4; ++i) {
        rs[i] += __shfl_xor_sync(0xffffffffu, rs[i], 1);
        rs[i] += __shfl_xor_sync(0xffffffffu, rs[i], 2);
    }
    float* red = (float*)(smem + OFF_RED);
    const int r0 = wm * 32 + (lid >> 2);
    if ((lid & 3) == 0 && wn == 0) {
        red[r0]      = rs[0];
        red[r0 + 8]  = rs[1];
        red[r0 + 16] = rs[2];
        red[r0 + 24] = rs[3];
    }
    __syncthreads();
    if ((lid & 3) == 0 && wn == 1) {
        const float vb = Vb[0];
        g_scores[m0 + r0]      = red[r0]      + rs[0] + vb;
        g_scores[m0 + r0 + 8]  = red[r0 + 8]  + rs[1] + vb;
        g_scores[m0 + r0 + 16] = red[r0 + 16] + rs[2] + vb;
        g_scores[m0 + r0 + 24] = red[r0 + 24] + rs[3] + vb;
    }
}

// -------------------- softmax (mask as int32) --------------------------------
__global__ void softmax_kernel(const int* __restrict__ mask,
                               float* __restrict__ weights) {
    const int b = blockIdx.x;
    const int tid = threadIdx.x;
    __shared__ float red[256];

    float vals[8];
    float mx = -INFINITY;
#pragma unroll
    for (int i = 0; i < 8; ++i) {
        const int s = tid + i * 256;
        float sc = g_scores[b * Sn + s];
        if (mask[b * Sn + s] != 0) sc = -1e30f;
        vals[i] = sc;
        mx = fmaxf(mx, sc);
    }
    red[tid] = mx;
    __syncthreads();
    for (int o = 128; o; o >>= 1) {
        if (tid < o) red[tid] = fmaxf(red[tid], red[tid + o]);
        __syncthreads();
    }
    mx = red[0];
    __syncthreads();

    float sum = 0.f;
#pragma unroll
    for (int i = 0; i < 8; ++i) {
        vals[i] = __expf(vals[i] - mx);
        sum += vals[i];
    }
    red[tid] = sum;
    __syncthreads();
    for (int o = 128; o; o >>= 1) {
        if (tid < o) red[tid] += red[tid + o];
        __syncthreads();
    }
    const float inv = 1.0f / red[0];
#pragma unroll
    for (int i = 0; i < 8; ++i)
        weights[b * Sn + tid + i * 256] = vals[i] * inv;
}

// -------------------- weighted sum (fp32 enc for accuracy) -------------------
__global__ void weighted_kernel(const float* __restrict__ enc,
                                const float* __restrict__ weights,
                                float* __restrict__ out) {
    const int b = blockIdx.y;
    const int e = blockIdx.x * 256 + threadIdx.x;
    const int s0 = blockIdx.z * 256;

    __shared__ float w[256];
    w[threadIdx.x] = weights[b * Sn + s0 + threadIdx.x];
    __syncthreads();

    const float* ep = enc + (size_t)b * Sn * En + (size_t)s0 * En + e;
    float acc = 0.f;
#pragma unroll 8
    for (int s = 0; s < 256; ++s)
        acc = fmaf(w[s], ep[(size_t)s * En], acc);
    atomicAdd(&out[b * En + e], acc);
}

// -----------------------------------------------------------------------------
extern "C" void kernel_launch(void* const* d_in, const int* in_sizes, int n_in,
                              void* d_out, int out_size) {
    const float* hidden = (const float*)d_in[0];
    const float* enc    = (const float*)d_in[1];
    const int*   mask   = (const int*)d_in[2];
    const float* Mw     = (const float*)d_in[3];
    const float* Mb     = (const float*)d_in[4];
    const float* Vw     = (const float*)d_in[5];
    const float* Vb     = (const float*)d_in[6];

    float* out_weighted = (float*)d_out;
    float* out_weights  = (float*)d_out + Bn * En;

    cudaFuncSetAttribute(scores_mma_kernel,
                         cudaFuncAttributeMaxDynamicSharedMemorySize, SMEM_SC);

    zero_out_kernel<<<(Bn * En + 255) / 256, 256>>>(out_weighted, Bn * En);
    colsum_kernel<<<Hn / 256, 256>>>(Mw);
    hidc_kernel<<<(Bn * Hn) / 256, 256>>>(hidden, Mb);
    mwconv_kernel<<<(Hn * En) / 256, 256>>>(Mw);
    encconv_kernel<<<((size_t)Bn * Sn * En / 4) / 256, 256>>>(enc);

    scores_mma_kernel<<<(Bn * Sn) / BM, 256, SMEM_SC>>>(Vw, Vb);

    softmax_kernel<<<Bn, 256>>>(mask, out_weights);

    dim3 wgrid(En / 256, Bn, Sn / 256);
    weighted_kernel<<<wgrid, 256>>>(enc, out_weights, out_weighted);
}